// round 14
// baseline (speedup 1.0000x reference)
#include <cuda_runtime.h>
#include <cuda_bf16.h>
#include <math.h>
#include <stdint.h>

// Problem dims
#define BB 32
#define TT 128
#define EE 512
#define HH 1024
#define LDIM 256
#define LL 5000
#define LLP 5120
#define TB 4096
#define G4 4096

#define GRID_P 128

// ---------------- device scratch (no allocs allowed) ----------------
__device__ float  g_xg_enc[(size_t)G4 * TB];
__device__ float  g_xg_dec[(size_t)G4 * TB];
__device__ unsigned g_flags[GRID_P];           // distributed barrier flags
__device__ __align__(16) uint32_t g_hwp[2][2][32 * 512];

// GEMM operands in FRAGMENT-ORDER layout (bulk-copy sources, zero padding)
__device__ __align__(16) __nv_bfloat16 g_ws_hi[(size_t)LLP * HH];    // B-frag
__device__ __align__(16) __nv_bfloat16 g_ws_lo[(size_t)LLP * HH];
__device__ __align__(16) __nv_bfloat16 g_wihe_hi[(size_t)G4 * EE];   // A-frag
__device__ __align__(16) __nv_bfloat16 g_wihe_lo[(size_t)G4 * EE];
__device__ __align__(16) __nv_bfloat16 g_wihd_hi[(size_t)G4 * LDIM]; // A-frag
__device__ __align__(16) __nv_bfloat16 g_wihd_lo[(size_t)G4 * LDIM];
__device__ __align__(16) __nv_bfloat16 g_embg_hi[(size_t)TB * EE];   // B-frag
__device__ __align__(16) __nv_bfloat16 g_embg_lo[(size_t)TB * EE];
__device__ __align__(16) __nv_bfloat16 g_labg_hi[(size_t)TB * LDIM]; // B-frag
__device__ __align__(16) __nv_bfloat16 g_labg_lo[(size_t)TB * LDIM];
__device__ __align__(16) __nv_bfloat16 g_hs_hi[(size_t)TB * HH];     // A-frag
__device__ __align__(16) __nv_bfloat16 g_hs_lo[(size_t)TB * HH];

// device-side global selection (NEVER pass __device__ symbols from host!)
// 0=ws 1=wihe 2=wihd 3=embg 4=labg 5=hs
template <int SEL>
__device__ __forceinline__ __nv_bfloat16* sel_hi() {
    return SEL == 0 ? g_ws_hi : SEL == 1 ? g_wihe_hi : SEL == 2 ? g_wihd_hi
         : SEL == 3 ? g_embg_hi : SEL == 4 ? g_labg_hi : g_hs_hi;
}
template <int SEL>
__device__ __forceinline__ __nv_bfloat16* sel_lo() {
    return SEL == 0 ? g_ws_lo : SEL == 1 ? g_wihe_lo : SEL == 2 ? g_wihd_lo
         : SEL == 3 ? g_embg_lo : SEL == 4 ? g_labg_lo : g_hs_lo;
}

// ---- fragment-order index maps (H1 layout, hardware-verified round 9) ----
__device__ __forceinline__ size_t a_frag_idx(int row, int k, int R) {
    int chunk = k >> 5, ks = (k >> 4) & 1;
    int mt = row >> 4, rl = row & 15, kl = k & 15;
    int word = (rl >> 3) | ((kl >> 3) << 1);
    int lane = ((rl & 7) << 2) | ((kl & 7) >> 1);
    return ((((size_t)chunk * (R >> 4) + mt) * 2 + ks) * 32 + lane) * 8
           + word * 2 + (kl & 1);
}
__device__ __forceinline__ size_t b_frag_idx(int row, int k, int R) {
    int chunk = k >> 5, ks = (k >> 4) & 1;
    int nt = row >> 3, kl = k & 15;
    int word = kl >> 3;
    int lane = ((row & 7) << 2) | ((kl & 7) >> 1);
    return ((((size_t)chunk * (R >> 3) + nt) * 2 + ks) * 32 + lane) * 4
           + word * 2 + (kl & 1);
}

__device__ __forceinline__ float sigmoidf_(float x) { return 1.f / (1.f + expf(-x)); }

__device__ __forceinline__ uint32_t smem_u32(const void* p) {
    uint32_t a;
    asm("{ .reg .u64 t; cvta.to.shared.u64 t, %1; cvt.u32.u64 %0, t; }"
        : "=r"(a) : "l"(p));
    return a;
}

#define MMA16816(d, a0, a1, a2, a3, b0, b1) \
    asm volatile("mma.sync.aligned.m16n8k16.row.col.f32.bf16.bf16.f32 " \
        "{%0,%1,%2,%3}, {%4,%5,%6,%7}, {%8,%9}, {%0,%1,%2,%3};" \
        : "+f"((d)[0]), "+f"((d)[1]), "+f"((d)[2]), "+f"((d)[3]) \
        : "r"(a0), "r"(a1), "r"(a2), "r"(a3), "r"(b0), "r"(b1))

#define CP_ASYNC16(sa, ga) \
    asm volatile("cp.async.cg.shared.global [%0], [%1], 16;" :: "r"(sa), "l"(ga))
#define CP_COMMIT() asm volatile("cp.async.commit_group;")
#define CP_WAIT0() asm volatile("cp.async.wait_group 0;")
#define CP_WAIT1() asm volatile("cp.async.wait_group 1;")

#define CP_BULK(sa, ga, sz, mb) \
    asm volatile("cp.async.bulk.shared::cta.global.mbarrier::complete_tx::bytes " \
        "[%0], [%1], %2, [%3];" :: "r"(sa), "l"(ga), "r"(sz), "r"(mb) : "memory")
#define MBAR_INIT(a, c) \
    asm volatile("mbarrier.init.shared.b64 [%0], %1;" :: "r"(a), "r"(c) : "memory")
#define MBAR_EXPECT_TX(a, tx) \
    asm volatile("mbarrier.arrive.expect_tx.shared.b64 _, [%0], %1;" \
        :: "r"(a), "r"(tx) : "memory")
#define MBAR_WAIT(a, ph) do { \
    uint32_t _mb = (a), _p = (ph), _d; \
    asm volatile("{\n\t.reg .pred p;\n\t" \
        "mbarrier.try_wait.parity.acquire.cta.shared::cta.b64 p, [%1], %2;\n\t" \
        "selp.b32 %0,1,0,p;\n\t}" : "=r"(_d) : "r"(_mb), "r"(_p) : "memory"); \
    if (!_d) { \
        asm volatile("{\n\t.reg .pred P1;\n\tWL_%=:\n\t" \
            "mbarrier.try_wait.parity.acquire.cta.shared::cta.b64 P1, [%0], %1, 0x989680;\n\t" \
            "@P1 bra.uni WD_%=;\n\tbra.uni WL_%=;\n\tWD_%=:\n\t}" \
            :: "r"(_mb), "r"(_p) : "memory"); \
    } } while (0)

__device__ __forceinline__ uint32_t pkbf2_(float x, float y) {
    uint32_t lo = (uint32_t)__bfloat16_as_ushort(__float2bfloat16(x));
    uint32_t hi = (uint32_t)__bfloat16_as_ushort(__float2bfloat16(y));
    return lo | (hi << 16);
}
__device__ __forceinline__ float lof_(float x) {
    return x - __bfloat162float(__float2bfloat16(x));
}

// ---------------- zero initial state + barrier flags ----------------
__global__ void zero_state_kernel() {
    int i = blockIdx.x * blockDim.x + threadIdx.x;
    if (i < 2 * 32 * 512) ((uint32_t*)g_hwp)[i] = 0u;
    if (i < GRID_P) g_flags[i] = 0u;
}

// ---------------- fp32 -> (bf16 hi/lo), LAYOUT: 0=A-frag 1=B-frag ----
template <int SEL, int KD, int ROWS, int LAYOUT>
__global__ void conv_pad_kernel(const float* __restrict__ src, int n_src) {
    __nv_bfloat16* hi = sel_hi<SEL>();
    __nv_bfloat16* lo = sel_lo<SEL>();
    int i = blockIdx.x * blockDim.x + threadIdx.x;
    if (i >= ROWS * KD) return;
    float v = (i < n_src) ? src[i] : 0.f;
    __nv_bfloat16 h = __float2bfloat16(v);
    __nv_bfloat16 l = __float2bfloat16(v - __bfloat162float(h));
    int row = i / KD, k = i - row * KD;
    size_t d = (LAYOUT == 0) ? a_frag_idx(row, k, ROWS) : b_frag_idx(row, k, ROWS);
    hi[d] = h;
    lo[d] = l;
}

// ---------------- gather embedding rows + split-convert (B-frag dst) ----------------
template <int KDIM, int MODE>
__global__ void gather_conv_kernel(const int* __restrict__ idx,
                                   const float* __restrict__ emb) {
    __nv_bfloat16* hi = sel_hi<(MODE == 0) ? 3 : 4>();
    __nv_bfloat16* lo = sel_lo<(MODE == 0) ? 3 : 4>();
    int i = blockIdx.x * blockDim.x + threadIdx.x;
    if (i >= TB * KDIM) return;
    int r = i / KDIM, k = i - r * KDIM;
    int row;
    if (MODE == 0) {
        row = idx[r];
    } else {
        int t = r >> 5, b = r & 31;
        row = (t == 0) ? 1 : idx[b * TT + t - 1];
    }
    float v = emb[(size_t)row * KDIM + k];
    __nv_bfloat16 h = __float2bfloat16(v);
    size_t d = b_frag_idx(r, k, TB);
    hi[d] = h;
    lo[d] = __float2bfloat16(v - __bfloat162float(h));
}

// ---------------- split-bf16 GEMM, fragment-order operands, bulk staged ----------------
#define OPBA 8192
#define BUFB (4 * OPBA)
#define MM_SMEM (1024 + 2 * BUFB)

template <int KDIM, int BIASMODE, int ASEL, int BSEL, int OUTSEL,
          int AROWS, int BROWS>
__global__ __launch_bounds__(256) void mma_gemm_kernel(
    float* __restrict__ out_param, int ldout, int nvalid,
    const float* __restrict__ bn,
    const float* __restrict__ bm1, const float* __restrict__ bm2)
{
    constexpr int NC = KDIM / 32;
    extern __shared__ char smem[];
    uint32_t sb = smem_u32(smem);
    uint32_t mb0 = sb, mb1 = sb + 8;

    float* out = (OUTSEL == 0) ? out_param : (OUTSEL == 1) ? g_xg_enc : g_xg_dec;

    const int tid = threadIdx.x, lane = tid & 31, wid = tid >> 5;
    const int wm = wid & 1, wn = wid >> 1;
    const int mBase = blockIdx.y * 128, nBase = blockIdx.x * 128;

    const __nv_bfloat16* srcs[4] = {sel_hi<ASEL>(), sel_lo<ASEL>(),
                                    sel_hi<BSEL>(), sel_lo<BSEL>()};

    if (tid == 0) { MBAR_INIT(mb0, 1); MBAR_INIT(mb1, 1); }
    __syncthreads();

    auto issue = [&](int c, int buf) {
        if (tid == 0) {
            uint32_t mb = buf ? mb1 : mb0;
            MBAR_EXPECT_TX(mb, (uint32_t)BUFB);
#pragma unroll
            for (int op = 0; op < 4; op++) {
                size_t rows = (op < 2) ? (size_t)AROWS : (size_t)BROWS;
                int rbase = (op < 2) ? mBase : nBase;
                const char* g = (const char*)srcs[op] +
                                ((size_t)c * rows + rbase) * 64;
                CP_BULK(sb + 1024 + buf * BUFB + op * OPBA, g, (uint32_t)OPBA, mb);
            }
        }
    };

    float acc[4][4][4];
#pragma unroll
    for (int mt = 0; mt < 4; mt++)
#pragma unroll
        for (int nt = 0; nt < 4; nt++)
#pragma unroll
            for (int q = 0; q < 4; q++) acc[mt][nt][q] = 0.f;

    issue(0, 0);
    issue(1, 1);
    for (int c = 0; c < NC; c++) {
        int buf = c & 1;
        MBAR_WAIT(buf ? mb1 : mb0, (c >> 1) & 1);

        uint32_t sbb = sb + 1024 + buf * BUFB;
        uint32_t sAh = sbb, sAl = sbb + OPBA;
        uint32_t sBh = sbb + 2 * OPBA, sBl = sbb + 3 * OPBA;

#pragma unroll
        for (int ks = 0; ks < 2; ks++) {
            uint2 bh[4], bl[4];
#pragma unroll
            for (int ntl = 0; ntl < 4; ntl++) {
                uint32_t off = (uint32_t)(((wn * 4 + ntl) * 2 + ks) * 256 + lane * 8);
                bh[ntl] = *(const uint2*)(smem + (sBh - sb) + off);
                bl[ntl] = *(const uint2*)(smem + (sBl - sb) + off);
            }
#pragma unroll
            for (int mtl = 0; mtl < 4; mtl++) {
                uint32_t off = (uint32_t)(((wm * 4 + mtl) * 2 + ks) * 512 + lane * 16);
                uint4 ah = *(const uint4*)(smem + (sAh - sb) + off);
                uint4 al = *(const uint4*)(smem + (sAl - sb) + off);
#pragma unroll
                for (int ntl = 0; ntl < 4; ntl++) {
                    MMA16816(acc[mtl][ntl], ah.x, ah.y, ah.z, ah.w,
                             bh[ntl].x, bh[ntl].y);
                    MMA16816(acc[mtl][ntl], ah.x, ah.y, ah.z, ah.w,
                             bl[ntl].x, bl[ntl].y);
                    MMA16816(acc[mtl][ntl], al.x, al.y, al.z, al.w,
                             bh[ntl].x, bh[ntl].y);
                }
            }
        }
        __syncthreads();
        if (c + 2 < NC) issue(c + 2, buf);
    }

#pragma unroll
    for (int mt = 0; mt < 4; mt++) {
        int m0 = mBase + wm * 64 + mt * 16 + (lane >> 2);
#pragma unroll
        for (int half = 0; half < 2; half++) {
            int gm = m0 + half * 8;
            float bm = 0.f;
            if (BIASMODE == 1) bm = bm1[gm] + bm2[gm];
#pragma unroll
            for (int nt = 0; nt < 4; nt++) {
                int gn = nBase + wn * 32 + nt * 8 + (lane & 3) * 2;
                float v0 = acc[mt][nt][half * 2 + 0];
                float v1 = acc[mt][nt][half * 2 + 1];
                if (BIASMODE == 0) {
                    if (gn < nvalid) {
                        float2 o = make_float2(v0 + bn[gn], v1 + bn[gn + 1]);
                        *(float2*)&out[(size_t)gm * ldout + gn] = o;
                    }
                } else {
                    float2 o = make_float2(v0 + bm, v1 + bm);
                    *(float2*)&out[(size_t)gm * ldout + gn] = o;
                }
            }
        }
    }
}

// ---------------- persistent split-bf16 HMMA LSTM recurrence ----------------
#define SM_WFRAG 0
#define SM_HBUF  131072
#define SM_CRED  180224
#define SM_CS    212992
#define SM_HT    214016
#define SM_TOT   215040

__global__ __launch_bounds__(256, 1) void lstm_hmma_kernel(
    const float* __restrict__ encW, const float* __restrict__ decW)
{
    extern __shared__ char sm8[];
    const int tid = threadIdx.x, lane = tid & 31, w = tid >> 5;
    const int jbase = blockIdx.x * 8;
    float* c_s  = (float*)(sm8 + SM_CS);
    float* htmp = (float*)(sm8 + SM_HT);
    float* cred = (float*)(sm8 + SM_CRED);

    // stage W_hh: read fp32, split to hi/lo fragment words in-kernel
    auto stage_w = [&](const float* W) {
        for (int ss = tid; ss < 8192; ss += 256) {
            int ls = ss & 31, hl = (ss >> 5) & 1, mt = (ss >> 6) & 1, kk = ss >> 7;
            int r0 = mt * 16 + (ls >> 2);
            int kw0 = kk * 8 + (ls & 3);
            int gA = (r0 & 3) * HH + jbase + (r0 >> 2);
            int gB = ((r0 + 8) & 3) * HH + jbase + ((r0 + 8) >> 2);
            float2 a0 = *(const float2*)&W[(size_t)gA * HH + kw0 * 2];
            float2 b0 = *(const float2*)&W[(size_t)gB * HH + kw0 * 2];
            float2 a1 = *(const float2*)&W[(size_t)gA * HH + (kw0 + 4) * 2];
            float2 b1 = *(const float2*)&W[(size_t)gB * HH + (kw0 + 4) * 2];
            uint4 v;
            if (hl == 0) {
                v.x = pkbf2_(a0.x, a0.y); v.y = pkbf2_(b0.x, b0.y);
                v.z = pkbf2_(a1.x, a1.y); v.w = pkbf2_(b1.x, b1.y);
            } else {
                v.x = pkbf2_(lof_(a0.x), lof_(a0.y));
                v.y = pkbf2_(lof_(b0.x), lof_(b0.y));
                v.z = pkbf2_(lof_(a1.x), lof_(a1.y));
                v.w = pkbf2_(lof_(b1.x), lof_(b1.y));
            }
            *(uint4*)(sm8 + SM_WFRAG + ss * 16) = v;
        }
    };

    stage_w(encW);
    c_s[tid] = 0.f;
    __syncthreads();

    for (int s = 0; s < 256; s++) {
        if (s == 128) { __syncthreads(); stage_w(decW); __syncthreads(); }
        const int pp = s & 1, t = s & 127;
        const uint32_t* hsrc0 = g_hwp[pp][0];
        const uint32_t* hsrc1 = g_hwp[pp][1];

        auto stage_h = [&](int g) {
            char* dst0 = sm8 + SM_HBUF + w * 6144 + (g & 1) * 3072;
#pragma unroll
            for (int u = 0; u < 4; u++) {
                int e = u * 32 + lane;
                int hl = e >> 6, rem = e & 63;
                int bb = rem >> 1, seg = rem & 1;
                const uint32_t* src = (hl ? hsrc1 : hsrc0)
                    + bb * 512 + w * 64 + g * 8 + seg * 4;
                uint32_t sa = smem_u32(dst0 + hl * 1536 + (bb * 12 + seg * 4) * 4);
                CP_ASYNC16(sa, src);
            }
            CP_COMMIT();
        };

        float acc[2][4][4];
#pragma unroll
        for (int mt = 0; mt < 2; mt++)
#pragma unroll
            for (int nt = 0; nt < 4; nt++)
#pragma unroll
                for (int q = 0; q < 4; q++) acc[mt][nt][q] = 0.f;

        stage_h(0);
#pragma unroll
        for (int g = 0; g < 8; g++) {
            if (g < 7) { stage_h(g + 1); CP_WAIT1(); } else { CP_WAIT0(); }
            int sbase = SM_WFRAG + (w * 8 + g) * 2048;
            uint4 AH0 = *(uint4*)(sm8 + sbase + lane * 16);
            uint4 AL0 = *(uint4*)(sm8 + sbase + 512 + lane * 16);
            uint4 AH1 = *(uint4*)(sm8 + sbase + 1024 + lane * 16);
            uint4 AL1 = *(uint4*)(sm8 + sbase + 1536 + lane * 16);
            char* hb = sm8 + SM_HBUF + w * 6144 + (g & 1) * 3072;
#pragma unroll
            for (int nt = 0; nt < 4; nt++) {
                int bb = nt * 8 + (lane >> 2);
                uint32_t bh0 = *(uint32_t*)(hb + (bb * 12 + (lane & 3)) * 4);
                uint32_t bh1 = *(uint32_t*)(hb + (bb * 12 + (lane & 3) + 4) * 4);
                uint32_t bl0 = *(uint32_t*)(hb + 1536 + (bb * 12 + (lane & 3)) * 4);
                uint32_t bl1 = *(uint32_t*)(hb + 1536 + (bb * 12 + (lane & 3) + 4) * 4);
                MMA16816(acc[0][nt], AH0.x, AH0.y, AH0.z, AH0.w, bh0, bh1);
                MMA16816(acc[1][nt], AH1.x, AH1.y, AH1.z, AH1.w, bh0, bh1);
                MMA16816(acc[0][nt], AH0.x, AH0.y, AH0.z, AH0.w, bl0, bl1);
                MMA16816(acc[1][nt], AH1.x, AH1.y, AH1.z, AH1.w, bl0, bl1);
                MMA16816(acc[0][nt], AL0.x, AL0.y, AL0.z, AL0.w, bh0, bh1);
                MMA16816(acc[1][nt], AL1.x, AL1.y, AL1.z, AL1.w, bh0, bh1);
            }
        }

#pragma unroll
        for (int mt = 0; mt < 2; mt++)
#pragma unroll
            for (int nt = 0; nt < 4; nt++) {
                int rlo = mt * 16 + (lane >> 2);
                int c0 = nt * 8 + (lane & 3) * 2;
                int r1 = rlo, r2 = rlo + 8;
                int s1 = (r1 & 7) << 2, s2 = (r2 & 7) << 2;
                *(float2*)&cred[(w * 32 + r1) * 32 + (c0 ^ s1)] =
                    make_float2(acc[mt][nt][0], acc[mt][nt][1]);
                *(float2*)&cred[(w * 32 + r2) * 32 + (c0 ^ s2)] =
                    make_float2(acc[mt][nt][2], acc[mt][nt][3]);
            }
        __syncthreads();

        {
            int b = tid & 31, jx = tid >> 5;
            const float* xg = (s < 128) ? g_xg_enc : g_xg_dec;
            float sg[4];
#pragma unroll
            for (int gg = 0; gg < 4; gg++) {
                int row = jx * 4 + gg;
                int sw = (row & 7) << 2;
                float v = xg[(size_t)(gg * HH + jbase + jx) * TB + t * 32 + b];
#pragma unroll
                for (int ww = 0; ww < 8; ww++)
                    v += cred[(ww * 32 + row) * 32 + (b ^ sw)];
                sg[gg] = v;
            }
            float ig = sigmoidf_(sg[0]);
            float fg = sigmoidf_(sg[1]);
            float gv = tanhf(sg[2]);
            float og = sigmoidf_(sg[3]);
            float c = fg * c_s[jx * 32 + b] + ig * gv;
            c_s[jx * 32 + b] = c;
            float h = og * tanhf(c);
            htmp[jx * 32 + b] = h;
            if (s >= 128) {
                int rr = t * 32 + b;
                int j = jbase + jx;
                size_t d = a_frag_idx(rr, j, TB);
                __nv_bfloat16 hb16 = __float2bfloat16(h);
                g_hs_hi[d] = hb16;
                g_hs_lo[d] = __float2bfloat16(h - __bfloat162float(hb16));
            }
        }
        __syncthreads();

        {
            int hl = tid >> 7, q = tid & 127;
            int kpl = q >> 5, b = q & 31;
            float h0 = htmp[(2 * kpl) * 32 + b];
            float h1 = htmp[(2 * kpl + 1) * 32 + b];
            uint32_t word;
            if (hl == 0) {
                word = pkbf2_(h0, h1);
            } else {
                word = pkbf2_(lof_(h0), lof_(h1));
            }
            g_hwp[pp ^ 1][hl][b * 512 + (jbase >> 1) + kpl] = word;
        }
        __syncthreads();

        // distributed-flag grid barrier: one release store per CTA, parallel poll
        if (tid == 0) {
            asm volatile("st.release.gpu.global.u32 [%0], %1;"
                         :: "l"(&g_flags[blockIdx.x]), "r"((unsigned)(s + 1))
                         : "memory");
        }
        if (w == 0) {
            unsigned tgt = (unsigned)(s + 1);
            unsigned ok;
            do {
                unsigned v0, v1, v2, v3;
                asm volatile("ld.acquire.gpu.global.u32 %0, [%1];"
                             : "=r"(v0) : "l"(&g_flags[lane]) : "memory");
                asm volatile("ld.acquire.gpu.global.u32 %0, [%1];"
                             : "=r"(v1) : "l"(&g_flags[lane + 32]) : "memory");
                asm volatile("ld.acquire.gpu.global.u32 %0, [%1];"
                             : "=r"(v2) : "l"(&g_flags[lane + 64]) : "memory");
                asm volatile("ld.acquire.gpu.global.u32 %0, [%1];"
                             : "=r"(v3) : "l"(&g_flags[lane + 96]) : "memory");
                ok = (v0 >= tgt) && (v1 >= tgt) && (v2 >= tgt) && (v3 >= tgt);
            } while (!__all_sync(0xffffffffu, ok));
        }
        __syncthreads();
    }
}

// ---------------- host launcher ----------------
extern "C" void kernel_launch(void* const* d_in, const int* in_sizes, int n_in,
                              void* d_out, int out_size)
{
    const int*   sentence  = (const int*)d_in[0];
    const int*   label_seq = (const int*)d_in[1];
    const float* word_emb  = (const float*)d_in[2];
    const float* label_emb = (const float*)d_in[3];
    const float* enc_W_ih  = (const float*)d_in[4];
    const float* enc_W_hh  = (const float*)d_in[5];
    const float* enc_b_ih  = (const float*)d_in[6];
    const float* enc_b_hh  = (const float*)d_in[7];
    const float* dec_W_ih  = (const float*)d_in[8];
    const float* dec_W_hh  = (const float*)d_in[9];
    const float* dec_b_ih  = (const float*)d_in[10];
    const float* dec_b_hh  = (const float*)d_in[11];
    const float* W_score   = (const float*)d_in[12];
    const float* b_score   = (const float*)d_in[13];
    float* out = (float*)d_out;

    cudaFuncSetAttribute(lstm_hmma_kernel,
                         cudaFuncAttributeMaxDynamicSharedMemorySize, SM_TOT);
    cudaFuncSetAttribute(mma_gemm_kernel<EE, 1, 1, 3, 1, G4, TB>,
                         cudaFuncAttributeMaxDynamicSharedMemorySize, MM_SMEM);
    cudaFuncSetAttribute(mma_gemm_kernel<LDIM, 1, 2, 4, 2, G4, TB>,
                         cudaFuncAttributeMaxDynamicSharedMemorySize, MM_SMEM);
    cudaFuncSetAttribute(mma_gemm_kernel<HH, 0, 5, 0, 0, TB, LLP>,
                         cudaFuncAttributeMaxDynamicSharedMemorySize, MM_SMEM);

    zero_state_kernel<<<32, 1024>>>();
    conv_pad_kernel<1, EE, G4, 0><<<(G4 * EE + 255) / 256, 256>>>(enc_W_ih, G4 * EE);
    gather_conv_kernel<EE, 0><<<(TB * EE + 255) / 256, 256>>>(sentence, word_emb);
    mma_gemm_kernel<EE, 1, 1, 3, 1, G4, TB><<<dim3(TB / 128, G4 / 128), 256, MM_SMEM>>>(
        nullptr, TB, TB, nullptr, enc_b_ih, enc_b_hh);
    conv_pad_kernel<2, LDIM, G4, 0><<<(G4 * LDIM + 255) / 256, 256>>>(dec_W_ih, G4 * LDIM);
    gather_conv_kernel<LDIM, 1><<<(TB * LDIM + 255) / 256, 256>>>(label_seq, label_emb);
    mma_gemm_kernel<LDIM, 1, 2, 4, 2, G4, TB><<<dim3(TB / 128, G4 / 128), 256, MM_SMEM>>>(
        nullptr, TB, TB, nullptr, dec_b_ih, dec_b_hh);
    conv_pad_kernel<0, HH, LLP, 1><<<(LLP * HH + 255) / 256, 256>>>(W_score, LL * HH);

    // recurrence (persistent, split-bf16 HMMA, flag barrier)
    lstm_hmma_kernel<<<GRID_P, 256, SM_TOT>>>(enc_W_hh, dec_W_hh);

    // projection: out[r][l] = hs @ Ws^T + b_score
    mma_gemm_kernel<HH, 0, 5, 0, 0, TB, LLP><<<dim3(LLP / 128, TB / 128), 256, MM_SMEM>>>(
        out, LL, LL, b_score, nullptr, nullptr);
}

// round 15
// speedup vs baseline: 1.3676x; 1.3676x over previous
#include <cuda_runtime.h>
#include <cuda_bf16.h>
#include <math.h>
#include <stdint.h>

// Problem dims
#define BB 32
#define TT 128
#define EE 512
#define HH 1024
#define LDIM 256
#define LL 5000
#define LLP 5120
#define TB 4096
#define G4 4096

#define GRID_P 128

// ---------------- device scratch (no allocs allowed) ----------------
__device__ float  g_xg_enc[(size_t)G4 * TB];
__device__ float  g_xg_dec[(size_t)G4 * TB];
__device__ unsigned g_bar;                     // arrival counter
__device__ unsigned g_go;                      // go flag (last arriver writes)
__device__ __align__(16) uint32_t g_hwp[2][2][32 * 512];

// GEMM operands in FRAGMENT-ORDER layout (bulk-copy sources, zero padding)
__device__ __align__(16) __nv_bfloat16 g_ws_hi[(size_t)LLP * HH];    // B-frag
__device__ __align__(16) __nv_bfloat16 g_ws_lo[(size_t)LLP * HH];
__device__ __align__(16) __nv_bfloat16 g_wihe_hi[(size_t)G4 * EE];   // A-frag
__device__ __align__(16) __nv_bfloat16 g_wihe_lo[(size_t)G4 * EE];
__device__ __align__(16) __nv_bfloat16 g_wihd_hi[(size_t)G4 * LDIM]; // A-frag
__device__ __align__(16) __nv_bfloat16 g_wihd_lo[(size_t)G4 * LDIM];
__device__ __align__(16) __nv_bfloat16 g_embg_hi[(size_t)TB * EE];   // B-frag
__device__ __align__(16) __nv_bfloat16 g_embg_lo[(size_t)TB * EE];
__device__ __align__(16) __nv_bfloat16 g_labg_hi[(size_t)TB * LDIM]; // B-frag
__device__ __align__(16) __nv_bfloat16 g_labg_lo[(size_t)TB * LDIM];
__device__ __align__(16) __nv_bfloat16 g_hs_hi[(size_t)TB * HH];     // A-frag
__device__ __align__(16) __nv_bfloat16 g_hs_lo[(size_t)TB * HH];
// W_hh for recurrence (linear [row][K])
__device__ __align__(16) __nv_bfloat16 g_whhe_hi[(size_t)G4 * HH];
__device__ __align__(16) __nv_bfloat16 g_whhe_lo[(size_t)G4 * HH];
__device__ __align__(16) __nv_bfloat16 g_whhd_hi[(size_t)G4 * HH];
__device__ __align__(16) __nv_bfloat16 g_whhd_lo[(size_t)G4 * HH];

// device-side global selection (NEVER pass __device__ symbols from host!)
// 0=ws 1=wihe 2=wihd 3=embg 4=labg 5=hs 6=whhe 7=whhd
template <int SEL>
__device__ __forceinline__ __nv_bfloat16* sel_hi() {
    return SEL == 0 ? g_ws_hi : SEL == 1 ? g_wihe_hi : SEL == 2 ? g_wihd_hi
         : SEL == 3 ? g_embg_hi : SEL == 4 ? g_labg_hi : SEL == 5 ? g_hs_hi
         : SEL == 6 ? g_whhe_hi : g_whhd_hi;
}
template <int SEL>
__device__ __forceinline__ __nv_bfloat16* sel_lo() {
    return SEL == 0 ? g_ws_lo : SEL == 1 ? g_wihe_lo : SEL == 2 ? g_wihd_lo
         : SEL == 3 ? g_embg_lo : SEL == 4 ? g_labg_lo : SEL == 5 ? g_hs_lo
         : SEL == 6 ? g_whhe_lo : g_whhd_lo;
}

// ---- fragment-order index maps (H1 layout, hardware-verified round 9) ----
__device__ __forceinline__ size_t a_frag_idx(int row, int k, int R) {
    int chunk = k >> 5, ks = (k >> 4) & 1;
    int mt = row >> 4, rl = row & 15, kl = k & 15;
    int word = (rl >> 3) | ((kl >> 3) << 1);
    int lane = ((rl & 7) << 2) | ((kl & 7) >> 1);
    return ((((size_t)chunk * (R >> 4) + mt) * 2 + ks) * 32 + lane) * 8
           + word * 2 + (kl & 1);
}
__device__ __forceinline__ size_t b_frag_idx(int row, int k, int R) {
    int chunk = k >> 5, ks = (k >> 4) & 1;
    int nt = row >> 3, kl = k & 15;
    int word = kl >> 3;
    int lane = ((row & 7) << 2) | ((kl & 7) >> 1);
    return ((((size_t)chunk * (R >> 3) + nt) * 2 + ks) * 32 + lane) * 4
           + word * 2 + (kl & 1);
}

__device__ __forceinline__ float sigmoidf_(float x) { return 1.f / (1.f + expf(-x)); }

__device__ __forceinline__ uint32_t smem_u32(const void* p) {
    uint32_t a;
    asm("{ .reg .u64 t; cvta.to.shared.u64 t, %1; cvt.u32.u64 %0, t; }"
        : "=r"(a) : "l"(p));
    return a;
}

#define MMA16816(d, a0, a1, a2, a3, b0, b1) \
    asm volatile("mma.sync.aligned.m16n8k16.row.col.f32.bf16.bf16.f32 " \
        "{%0,%1,%2,%3}, {%4,%5,%6,%7}, {%8,%9}, {%0,%1,%2,%3};" \
        : "+f"((d)[0]), "+f"((d)[1]), "+f"((d)[2]), "+f"((d)[3]) \
        : "r"(a0), "r"(a1), "r"(a2), "r"(a3), "r"(b0), "r"(b1))

#define CP_ASYNC16(sa, ga) \
    asm volatile("cp.async.cg.shared.global [%0], [%1], 16;" :: "r"(sa), "l"(ga))
#define CP_COMMIT() asm volatile("cp.async.commit_group;")
#define CP_WAIT0() asm volatile("cp.async.wait_group 0;")
#define CP_WAIT1() asm volatile("cp.async.wait_group 1;")

#define CP_BULK(sa, ga, sz, mb) \
    asm volatile("cp.async.bulk.shared::cta.global.mbarrier::complete_tx::bytes " \
        "[%0], [%1], %2, [%3];" :: "r"(sa), "l"(ga), "r"(sz), "r"(mb) : "memory")
#define MBAR_INIT(a, c) \
    asm volatile("mbarrier.init.shared.b64 [%0], %1;" :: "r"(a), "r"(c) : "memory")
#define MBAR_EXPECT_TX(a, tx) \
    asm volatile("mbarrier.arrive.expect_tx.shared.b64 _, [%0], %1;" \
        :: "r"(a), "r"(tx) : "memory")
#define MBAR_WAIT(a, ph) do { \
    uint32_t _mb = (a), _p = (ph), _d; \
    asm volatile("{\n\t.reg .pred p;\n\t" \
        "mbarrier.try_wait.parity.acquire.cta.shared::cta.b64 p, [%1], %2;\n\t" \
        "selp.b32 %0,1,0,p;\n\t}" : "=r"(_d) : "r"(_mb), "r"(_p) : "memory"); \
    if (!_d) { \
        asm volatile("{\n\t.reg .pred P1;\n\tWL_%=:\n\t" \
            "mbarrier.try_wait.parity.acquire.cta.shared::cta.b64 P1, [%0], %1, 0x989680;\n\t" \
            "@P1 bra.uni WD_%=;\n\tbra.uni WL_%=;\n\tWD_%=:\n\t}" \
            :: "r"(_mb), "r"(_p) : "memory"); \
    } } while (0)

__device__ __forceinline__ uint32_t pkbf2_(float x, float y) {
    uint32_t lo = (uint32_t)__bfloat16_as_ushort(__float2bfloat16(x));
    uint32_t hi = (uint32_t)__bfloat16_as_ushort(__float2bfloat16(y));
    return lo | (hi << 16);
}
__device__ __forceinline__ float lof_(float x) {
    return x - __bfloat162float(__float2bfloat16(x));
}

// ---------------- zero initial state + barrier ----------------
__global__ void zero_state_kernel() {
    int i = blockIdx.x * blockDim.x + threadIdx.x;
    if (i < 2 * 32 * 512) ((uint32_t*)g_hwp)[i] = 0u;
    if (i == 0) { g_bar = 0u; g_go = 0u; }
}

// ---------------- fp32 -> (bf16 hi/lo), LAYOUT: 0=A-frag 1=B-frag 2=linear ----
template <int SEL, int KD, int ROWS, int LAYOUT>
__global__ void conv_pad_kernel(const float* __restrict__ src, int n_src) {
    __nv_bfloat16* hi = sel_hi<SEL>();
    __nv_bfloat16* lo = sel_lo<SEL>();
    int i = blockIdx.x * blockDim.x + threadIdx.x;
    if (i >= ROWS * KD) return;
    float v = (i < n_src) ? src[i] : 0.f;
    __nv_bfloat16 h = __float2bfloat16(v);
    __nv_bfloat16 l = __float2bfloat16(v - __bfloat162float(h));
    size_t d;
    if (LAYOUT == 2) {
        d = i;
    } else {
        int row = i / KD, k = i - row * KD;
        d = (LAYOUT == 0) ? a_frag_idx(row, k, ROWS) : b_frag_idx(row, k, ROWS);
    }
    hi[d] = h;
    lo[d] = l;
}

// ---------------- gather embedding rows + split-convert (B-frag dst) ----------------
template <int KDIM, int MODE>
__global__ void gather_conv_kernel(const int* __restrict__ idx,
                                   const float* __restrict__ emb) {
    __nv_bfloat16* hi = sel_hi<(MODE == 0) ? 3 : 4>();
    __nv_bfloat16* lo = sel_lo<(MODE == 0) ? 3 : 4>();
    int i = blockIdx.x * blockDim.x + threadIdx.x;
    if (i >= TB * KDIM) return;
    int r = i / KDIM, k = i - r * KDIM;
    int row;
    if (MODE == 0) {
        row = idx[r];
    } else {
        int t = r >> 5, b = r & 31;
        row = (t == 0) ? 1 : idx[b * TT + t - 1];
    }
    float v = emb[(size_t)row * KDIM + k];
    __nv_bfloat16 h = __float2bfloat16(v);
    size_t d = b_frag_idx(r, k, TB);
    hi[d] = h;
    lo[d] = __float2bfloat16(v - __bfloat162float(h));
}

// ---------------- split-bf16 GEMM, fragment-order operands, bulk staged ----------------
#define OPBA 8192
#define BUFB (4 * OPBA)
#define MM_SMEM (1024 + 2 * BUFB)

template <int KDIM, int BIASMODE, int ASEL, int BSEL, int OUTSEL,
          int AROWS, int BROWS>
__global__ __launch_bounds__(256) void mma_gemm_kernel(
    float* __restrict__ out_param, int ldout, int nvalid,
    const float* __restrict__ bn,
    const float* __restrict__ bm1, const float* __restrict__ bm2)
{
    constexpr int NC = KDIM / 32;
    extern __shared__ char smem[];
    uint32_t sb = smem_u32(smem);
    uint32_t mb0 = sb, mb1 = sb + 8;

    float* out = (OUTSEL == 0) ? out_param : (OUTSEL == 1) ? g_xg_enc : g_xg_dec;

    const int tid = threadIdx.x, lane = tid & 31, wid = tid >> 5;
    const int wm = wid & 1, wn = wid >> 1;
    const int mBase = blockIdx.y * 128, nBase = blockIdx.x * 128;

    const __nv_bfloat16* srcs[4] = {sel_hi<ASEL>(), sel_lo<ASEL>(),
                                    sel_hi<BSEL>(), sel_lo<BSEL>()};

    if (tid == 0) { MBAR_INIT(mb0, 1); MBAR_INIT(mb1, 1); }
    __syncthreads();

    auto issue = [&](int c, int buf) {
        if (tid == 0) {
            uint32_t mb = buf ? mb1 : mb0;
            MBAR_EXPECT_TX(mb, (uint32_t)BUFB);
#pragma unroll
            for (int op = 0; op < 4; op++) {
                size_t rows = (op < 2) ? (size_t)AROWS : (size_t)BROWS;
                int rbase = (op < 2) ? mBase : nBase;
                const char* g = (const char*)srcs[op] +
                                ((size_t)c * rows + rbase) * 64;
                CP_BULK(sb + 1024 + buf * BUFB + op * OPBA, g, (uint32_t)OPBA, mb);
            }
        }
    };

    float acc[4][4][4];
#pragma unroll
    for (int mt = 0; mt < 4; mt++)
#pragma unroll
        for (int nt = 0; nt < 4; nt++)
#pragma unroll
            for (int q = 0; q < 4; q++) acc[mt][nt][q] = 0.f;

    issue(0, 0);
    issue(1, 1);
    for (int c = 0; c < NC; c++) {
        int buf = c & 1;
        MBAR_WAIT(buf ? mb1 : mb0, (c >> 1) & 1);

        uint32_t sbb = sb + 1024 + buf * BUFB;
        uint32_t sAh = sbb, sAl = sbb + OPBA;
        uint32_t sBh = sbb + 2 * OPBA, sBl = sbb + 3 * OPBA;

#pragma unroll
        for (int ks = 0; ks < 2; ks++) {
            uint2 bh[4], bl[4];
#pragma unroll
            for (int ntl = 0; ntl < 4; ntl++) {
                uint32_t off = (uint32_t)(((wn * 4 + ntl) * 2 + ks) * 256 + lane * 8);
                bh[ntl] = *(const uint2*)(smem + (sBh - sb) + off);
                bl[ntl] = *(const uint2*)(smem + (sBl - sb) + off);
            }
#pragma unroll
            for (int mtl = 0; mtl < 4; mtl++) {
                uint32_t off = (uint32_t)(((wm * 4 + mtl) * 2 + ks) * 512 + lane * 16);
                uint4 ah = *(const uint4*)(smem + (sAh - sb) + off);
                uint4 al = *(const uint4*)(smem + (sAl - sb) + off);
#pragma unroll
                for (int ntl = 0; ntl < 4; ntl++) {
                    MMA16816(acc[mtl][ntl], ah.x, ah.y, ah.z, ah.w,
                             bh[ntl].x, bh[ntl].y);
                    MMA16816(acc[mtl][ntl], ah.x, ah.y, ah.z, ah.w,
                             bl[ntl].x, bl[ntl].y);
                    MMA16816(acc[mtl][ntl], al.x, al.y, al.z, al.w,
                             bh[ntl].x, bh[ntl].y);
                }
            }
        }
        __syncthreads();
        if (c + 2 < NC) issue(c + 2, buf);
    }

#pragma unroll
    for (int mt = 0; mt < 4; mt++) {
        int m0 = mBase + wm * 64 + mt * 16 + (lane >> 2);
#pragma unroll
        for (int half = 0; half < 2; half++) {
            int gm = m0 + half * 8;
            float bm = 0.f;
            if (BIASMODE == 1) bm = bm1[gm] + bm2[gm];
#pragma unroll
            for (int nt = 0; nt < 4; nt++) {
                int gn = nBase + wn * 32 + nt * 8 + (lane & 3) * 2;
                float v0 = acc[mt][nt][half * 2 + 0];
                float v1 = acc[mt][nt][half * 2 + 1];
                if (BIASMODE == 0) {
                    if (gn < nvalid) {
                        float2 o = make_float2(v0 + bn[gn], v1 + bn[gn + 1]);
                        *(float2*)&out[(size_t)gm * ldout + gn] = o;
                    }
                } else {
                    float2 o = make_float2(v0 + bm, v1 + bm);
                    *(float2*)&out[(size_t)gm * ldout + gn] = o;
                }
            }
        }
    }
}

// ---------------- persistent split-bf16 HMMA LSTM recurrence ----------------
#define SM_WFRAG 0
#define SM_HBUF  131072
#define SM_CRED  180224
#define SM_CS    212992
#define SM_HT    214016
#define SM_TOT   215040

__global__ __launch_bounds__(256, 1) void lstm_hmma_kernel()
{
    extern __shared__ char sm8[];
    const int tid = threadIdx.x, lane = tid & 31, w = tid >> 5;
    const int jbase = blockIdx.x * 8;
    float* c_s  = (float*)(sm8 + SM_CS);
    float* htmp = (float*)(sm8 + SM_HT);
    float* cred = (float*)(sm8 + SM_CRED);

    auto stage_w = [&](int phase) {
        const uint32_t* whi = (const uint32_t*)(phase ? g_whhd_hi : g_whhe_hi);
        const uint32_t* wlo = (const uint32_t*)(phase ? g_whhd_lo : g_whhe_lo);
        for (int ss = tid; ss < 8192; ss += 256) {
            int ls = ss & 31, hl = (ss >> 5) & 1, mt = (ss >> 6) & 1, kk = ss >> 7;
            const uint32_t* W2 = hl ? wlo : whi;
            int r0 = mt * 16 + (ls >> 2);
            int kw0 = kk * 8 + (ls & 3);
            int gA = (r0 & 3) * HH + jbase + (r0 >> 2);
            int gB = ((r0 + 8) & 3) * HH + jbase + ((r0 + 8) >> 2);
            uint4 v;
            v.x = W2[(size_t)gA * 512 + kw0];
            v.y = W2[(size_t)gB * 512 + kw0];
            v.z = W2[(size_t)gA * 512 + kw0 + 4];
            v.w = W2[(size_t)gB * 512 + kw0 + 4];
            *(uint4*)(sm8 + SM_WFRAG + ss * 16) = v;
        }
    };

    stage_w(0);
    c_s[tid] = 0.f;
    __syncthreads();

    for (int s = 0; s < 256; s++) {
        if (s == 128) { __syncthreads(); stage_w(1); __syncthreads(); }
        const int pp = s & 1, t = s & 127;
        const uint32_t* hsrc0 = g_hwp[pp][0];
        const uint32_t* hsrc1 = g_hwp[pp][1];

        // ---- xg prefetch for this step (independent of h) ----
        float xgv[4];
        {
            int b = tid & 31, jx = tid >> 5;
            const float* xg = (s < 128) ? g_xg_enc : g_xg_dec;
#pragma unroll
            for (int gg = 0; gg < 4; gg++)
                xgv[gg] = xg[(size_t)(gg * HH + jbase + jx) * TB + t * 32 + b];
        }

        auto stage_h = [&](int g) {
            char* dst0 = sm8 + SM_HBUF + w * 6144 + (g & 1) * 3072;
#pragma unroll
            for (int u = 0; u < 4; u++) {
                int e = u * 32 + lane;
                int hl = e >> 6, rem = e & 63;
                int bb = rem >> 1, seg = rem & 1;
                const uint32_t* src = (hl ? hsrc1 : hsrc0)
                    + bb * 512 + w * 64 + g * 8 + seg * 4;
                uint32_t sa = smem_u32(dst0 + hl * 1536 + (bb * 12 + seg * 4) * 4);
                CP_ASYNC16(sa, src);
            }
            CP_COMMIT();
        };

        float acc[2][4][4];
#pragma unroll
        for (int mt = 0; mt < 2; mt++)
#pragma unroll
            for (int nt = 0; nt < 4; nt++)
#pragma unroll
                for (int q = 0; q < 4; q++) acc[mt][nt][q] = 0.f;

        stage_h(0);
#pragma unroll
        for (int g = 0; g < 8; g++) {
            if (g < 7) { stage_h(g + 1); CP_WAIT1(); } else { CP_WAIT0(); }
            int sbase = SM_WFRAG + (w * 8 + g) * 2048;
            uint4 AH0 = *(uint4*)(sm8 + sbase + lane * 16);
            uint4 AL0 = *(uint4*)(sm8 + sbase + 512 + lane * 16);
            uint4 AH1 = *(uint4*)(sm8 + sbase + 1024 + lane * 16);
            uint4 AL1 = *(uint4*)(sm8 + sbase + 1536 + lane * 16);
            char* hb = sm8 + SM_HBUF + w * 6144 + (g & 1) * 3072;
#pragma unroll
            for (int nt = 0; nt < 4; nt++) {
                int bb = nt * 8 + (lane >> 2);
                uint32_t bh0 = *(uint32_t*)(hb + (bb * 12 + (lane & 3)) * 4);
                uint32_t bh1 = *(uint32_t*)(hb + (bb * 12 + (lane & 3) + 4) * 4);
                uint32_t bl0 = *(uint32_t*)(hb + 1536 + (bb * 12 + (lane & 3)) * 4);
                uint32_t bl1 = *(uint32_t*)(hb + 1536 + (bb * 12 + (lane & 3) + 4) * 4);
                MMA16816(acc[0][nt], AH0.x, AH0.y, AH0.z, AH0.w, bh0, bh1);
                MMA16816(acc[1][nt], AH1.x, AH1.y, AH1.z, AH1.w, bh0, bh1);
                MMA16816(acc[0][nt], AH0.x, AH0.y, AH0.z, AH0.w, bl0, bl1);
                MMA16816(acc[1][nt], AH1.x, AH1.y, AH1.z, AH1.w, bl0, bl1);
                MMA16816(acc[0][nt], AL0.x, AL0.y, AL0.z, AL0.w, bh0, bh1);
                MMA16816(acc[1][nt], AL1.x, AL1.y, AL1.z, AL1.w, bh0, bh1);
            }
        }

#pragma unroll
        for (int mt = 0; mt < 2; mt++)
#pragma unroll
            for (int nt = 0; nt < 4; nt++) {
                int rlo = mt * 16 + (lane >> 2);
                int c0 = nt * 8 + (lane & 3) * 2;
                int r1 = rlo, r2 = rlo + 8;
                int s1 = (r1 & 7) << 2, s2 = (r2 & 7) << 2;
                *(float2*)&cred[(w * 32 + r1) * 32 + (c0 ^ s1)] =
                    make_float2(acc[mt][nt][0], acc[mt][nt][1]);
                *(float2*)&cred[(w * 32 + r2) * 32 + (c0 ^ s2)] =
                    make_float2(acc[mt][nt][2], acc[mt][nt][3]);
            }
        __syncthreads();

        {
            int b = tid & 31, jx = tid >> 5;
            float sg[4];
#pragma unroll
            for (int gg = 0; gg < 4; gg++) {
                int row = jx * 4 + gg;
                int sw = (row & 7) << 2;
                float v = xgv[gg];
#pragma unroll
                for (int ww = 0; ww < 8; ww++)
                    v += cred[(ww * 32 + row) * 32 + (b ^ sw)];
                sg[gg] = v;
            }
            float ig = sigmoidf_(sg[0]);
            float fg = sigmoidf_(sg[1]);
            float gv = tanhf(sg[2]);
            float og = sigmoidf_(sg[3]);
            float c = fg * c_s[jx * 32 + b] + ig * gv;
            c_s[jx * 32 + b] = c;
            float h = og * tanhf(c);
            htmp[jx * 32 + b] = h;
            if (s >= 128) {
                int rr = t * 32 + b;
                int j = jbase + jx;
                size_t d = a_frag_idx(rr, j, TB);
                __nv_bfloat16 hb16 = __float2bfloat16(h);
                g_hs_hi[d] = hb16;
                g_hs_lo[d] = __float2bfloat16(h - __bfloat162float(hb16));
            }
        }
        __syncthreads();

        {
            int hl = tid >> 7, q = tid & 127;
            int kpl = q >> 5, b = q & 31;
            float h0 = htmp[(2 * kpl) * 32 + b];
            float h1 = htmp[(2 * kpl + 1) * 32 + b];
            uint32_t word;
            if (hl == 0) {
                word = pkbf2_(h0, h1);
            } else {
                word = pkbf2_(lof_(h0), lof_(h1));
            }
            g_hwp[pp ^ 1][hl][b * 512 + (jbase >> 1) + kpl] = word;
        }
        __syncthreads();

        // grid barrier: counter arrive; LAST arriver writes go-flag; poll quiet flag
        if (tid == 0) {
            unsigned old;
            asm volatile("atom.release.gpu.global.add.u32 %0, [%1], 1;"
                         : "=r"(old) : "l"(&g_bar) : "memory");
            unsigned target = (unsigned)(s + 1) * GRID_P;
            if (old == target - 1) {
                asm volatile("st.release.gpu.global.u32 [%0], %1;"
                             :: "l"(&g_go), "r"((unsigned)(s + 1)) : "memory");
            }
            unsigned v;
            do {
                asm volatile("ld.acquire.gpu.global.u32 %0, [%1];"
                             : "=r"(v) : "l"(&g_go) : "memory");
            } while (v < (unsigned)(s + 1));
        }
        __syncthreads();
    }
}

// ---------------- host launcher ----------------
extern "C" void kernel_launch(void* const* d_in, const int* in_sizes, int n_in,
                              void* d_out, int out_size)
{
    const int*   sentence  = (const int*)d_in[0];
    const int*   label_seq = (const int*)d_in[1];
    const float* word_emb  = (const float*)d_in[2];
    const float* label_emb = (const float*)d_in[3];
    const float* enc_W_ih  = (const float*)d_in[4];
    const float* enc_W_hh  = (const float*)d_in[5];
    const float* enc_b_ih  = (const float*)d_in[6];
    const float* enc_b_hh  = (const float*)d_in[7];
    const float* dec_W_ih  = (const float*)d_in[8];
    const float* dec_W_hh  = (const float*)d_in[9];
    const float* dec_b_ih  = (const float*)d_in[10];
    const float* dec_b_hh  = (const float*)d_in[11];
    const float* W_score   = (const float*)d_in[12];
    const float* b_score   = (const float*)d_in[13];
    float* out = (float*)d_out;

    cudaFuncSetAttribute(lstm_hmma_kernel,
                         cudaFuncAttributeMaxDynamicSharedMemorySize, SM_TOT);
    cudaFuncSetAttribute(mma_gemm_kernel<EE, 1, 1, 3, 1, G4, TB>,
                         cudaFuncAttributeMaxDynamicSharedMemorySize, MM_SMEM);
    cudaFuncSetAttribute(mma_gemm_kernel<LDIM, 1, 2, 4, 2, G4, TB>,
                         cudaFuncAttributeMaxDynamicSharedMemorySize, MM_SMEM);
    cudaFuncSetAttribute(mma_gemm_kernel<HH, 0, 5, 0, 0, TB, LLP>,
                         cudaFuncAttributeMaxDynamicSharedMemorySize, MM_SMEM);

    zero_state_kernel<<<32, 1024>>>();
    conv_pad_kernel<1, EE, G4, 0><<<(G4 * EE + 255) / 256, 256>>>(enc_W_ih, G4 * EE);
    gather_conv_kernel<EE, 0><<<(TB * EE + 255) / 256, 256>>>(sentence, word_emb);
    mma_gemm_kernel<EE, 1, 1, 3, 1, G4, TB><<<dim3(TB / 128, G4 / 128), 256, MM_SMEM>>>(
        nullptr, TB, TB, nullptr, enc_b_ih, enc_b_hh);
    conv_pad_kernel<2, LDIM, G4, 0><<<(G4 * LDIM + 255) / 256, 256>>>(dec_W_ih, G4 * LDIM);
    gather_conv_kernel<LDIM, 1><<<(TB * LDIM + 255) / 256, 256>>>(label_seq, label_emb);
    mma_gemm_kernel<LDIM, 1, 2, 4, 2, G4, TB><<<dim3(TB / 128, G4 / 128), 256, MM_SMEM>>>(
        nullptr, TB, TB, nullptr, dec_b_ih, dec_b_hh);
    conv_pad_kernel<0, HH, LLP, 1><<<(LLP * HH + 255) / 256, 256>>>(W_score, LL * HH);
    conv_pad_kernel<6, HH, G4, 2><<<(G4 * HH + 255) / 256, 256>>>(enc_W_hh, G4 * HH);
    conv_pad_kernel<7, HH, G4, 2><<<(G4 * HH + 255) / 256, 256>>>(dec_W_hh, G4 * HH);

    // recurrence (persistent, split-bf16 HMMA, go-flag barrier)
    lstm_hmma_kernel<<<GRID_P, 256, SM_TOT>>>();

    // projection: out[r][l] = hs @ Ws^T + b_score
    mma_gemm_kernel<HH, 0, 5, 0, 0, TB, LLP><<<dim3(LLP / 128, TB / 128), 256, MM_SMEM>>>(
        out, LL, LL, b_score, nullptr, nullptr);
}

// round 16
// speedup vs baseline: 1.8174x; 1.3289x over previous
#include <cuda_runtime.h>
#include <cuda_bf16.h>
#include <math.h>
#include <stdint.h>

// Problem dims
#define BB 32
#define TT 128
#define EE 512
#define HH 1024
#define LDIM 256
#define LL 5000
#define LLP 5120
#define TB 4096
#define G4 4096

#define GRID_P 128

// ---------------- device scratch (no allocs allowed) ----------------
__device__ float  g_xg_enc[(size_t)G4 * TB];
__device__ float  g_xg_dec[(size_t)G4 * TB];
__device__ unsigned g_bar;
// h ping-pong, kp-major: [pp][hl][kp*32 + b]  (b contiguous -> dense lines)
__device__ __align__(16) uint32_t g_hwp[2][2][512 * 32];

// GEMM operands in FRAGMENT-ORDER layout (bulk-copy sources, zero padding)
__device__ __align__(16) __nv_bfloat16 g_ws_hi[(size_t)LLP * HH];    // B-frag
__device__ __align__(16) __nv_bfloat16 g_ws_lo[(size_t)LLP * HH];
__device__ __align__(16) __nv_bfloat16 g_wihe_hi[(size_t)G4 * EE];   // A-frag
__device__ __align__(16) __nv_bfloat16 g_wihe_lo[(size_t)G4 * EE];
__device__ __align__(16) __nv_bfloat16 g_wihd_hi[(size_t)G4 * LDIM]; // A-frag
__device__ __align__(16) __nv_bfloat16 g_wihd_lo[(size_t)G4 * LDIM];
__device__ __align__(16) __nv_bfloat16 g_embg_hi[(size_t)TB * EE];   // B-frag
__device__ __align__(16) __nv_bfloat16 g_embg_lo[(size_t)TB * EE];
__device__ __align__(16) __nv_bfloat16 g_labg_hi[(size_t)TB * LDIM]; // B-frag
__device__ __align__(16) __nv_bfloat16 g_labg_lo[(size_t)TB * LDIM];
__device__ __align__(16) __nv_bfloat16 g_hs_hi[(size_t)TB * HH];     // A-frag
__device__ __align__(16) __nv_bfloat16 g_hs_lo[(size_t)TB * HH];
// W_hh for recurrence (linear [row][K])
__device__ __align__(16) __nv_bfloat16 g_whhe_hi[(size_t)G4 * HH];
__device__ __align__(16) __nv_bfloat16 g_whhe_lo[(size_t)G4 * HH];
__device__ __align__(16) __nv_bfloat16 g_whhd_hi[(size_t)G4 * HH];
__device__ __align__(16) __nv_bfloat16 g_whhd_lo[(size_t)G4 * HH];

// device-side global selection (NEVER pass __device__ symbols from host!)
// 0=ws 1=wihe 2=wihd 3=embg 4=labg 5=hs 6=whhe 7=whhd
template <int SEL>
__device__ __forceinline__ __nv_bfloat16* sel_hi() {
    return SEL == 0 ? g_ws_hi : SEL == 1 ? g_wihe_hi : SEL == 2 ? g_wihd_hi
         : SEL == 3 ? g_embg_hi : SEL == 4 ? g_labg_hi : SEL == 5 ? g_hs_hi
         : SEL == 6 ? g_whhe_hi : g_whhd_hi;
}
template <int SEL>
__device__ __forceinline__ __nv_bfloat16* sel_lo() {
    return SEL == 0 ? g_ws_lo : SEL == 1 ? g_wihe_lo : SEL == 2 ? g_wihd_lo
         : SEL == 3 ? g_embg_lo : SEL == 4 ? g_labg_lo : SEL == 5 ? g_hs_lo
         : SEL == 6 ? g_whhe_lo : g_whhd_lo;
}

// ---- fragment-order index maps (H1 layout, hardware-verified round 9) ----
__device__ __forceinline__ size_t a_frag_idx(int row, int k, int R) {
    int chunk = k >> 5, ks = (k >> 4) & 1;
    int mt = row >> 4, rl = row & 15, kl = k & 15;
    int word = (rl >> 3) | ((kl >> 3) << 1);
    int lane = ((rl & 7) << 2) | ((kl & 7) >> 1);
    return ((((size_t)chunk * (R >> 4) + mt) * 2 + ks) * 32 + lane) * 8
           + word * 2 + (kl & 1);
}
__device__ __forceinline__ size_t b_frag_idx(int row, int k, int R) {
    int chunk = k >> 5, ks = (k >> 4) & 1;
    int nt = row >> 3, kl = k & 15;
    int word = kl >> 3;
    int lane = ((row & 7) << 2) | ((kl & 7) >> 1);
    return ((((size_t)chunk * (R >> 3) + nt) * 2 + ks) * 32 + lane) * 4
           + word * 2 + (kl & 1);
}

__device__ __forceinline__ float sigmoidf_(float x) { return 1.f / (1.f + expf(-x)); }

__device__ __forceinline__ uint32_t smem_u32(const void* p) {
    uint32_t a;
    asm("{ .reg .u64 t; cvta.to.shared.u64 t, %1; cvt.u32.u64 %0, t; }"
        : "=r"(a) : "l"(p));
    return a;
}

#define MMA16816(d, a0, a1, a2, a3, b0, b1) \
    asm volatile("mma.sync.aligned.m16n8k16.row.col.f32.bf16.bf16.f32 " \
        "{%0,%1,%2,%3}, {%4,%5,%6,%7}, {%8,%9}, {%0,%1,%2,%3};" \
        : "+f"((d)[0]), "+f"((d)[1]), "+f"((d)[2]), "+f"((d)[3]) \
        : "r"(a0), "r"(a1), "r"(a2), "r"(a3), "r"(b0), "r"(b1))

#define CP_ASYNC16(sa, ga) \
    asm volatile("cp.async.cg.shared.global [%0], [%1], 16;" :: "r"(sa), "l"(ga))
#define CP_COMMIT() asm volatile("cp.async.commit_group;")
#define CP_WAIT0() asm volatile("cp.async.wait_group 0;")
#define CP_WAIT1() asm volatile("cp.async.wait_group 1;")

#define CP_BULK(sa, ga, sz, mb) \
    asm volatile("cp.async.bulk.shared::cta.global.mbarrier::complete_tx::bytes " \
        "[%0], [%1], %2, [%3];" :: "r"(sa), "l"(ga), "r"(sz), "r"(mb) : "memory")
#define MBAR_INIT(a, c) \
    asm volatile("mbarrier.init.shared.b64 [%0], %1;" :: "r"(a), "r"(c) : "memory")
#define MBAR_EXPECT_TX(a, tx) \
    asm volatile("mbarrier.arrive.expect_tx.shared.b64 _, [%0], %1;" \
        :: "r"(a), "r"(tx) : "memory")
#define MBAR_WAIT(a, ph) do { \
    uint32_t _mb = (a), _p = (ph), _d; \
    asm volatile("{\n\t.reg .pred p;\n\t" \
        "mbarrier.try_wait.parity.acquire.cta.shared::cta.b64 p, [%1], %2;\n\t" \
        "selp.b32 %0,1,0,p;\n\t}" : "=r"(_d) : "r"(_mb), "r"(_p) : "memory"); \
    if (!_d) { \
        asm volatile("{\n\t.reg .pred P1;\n\tWL_%=:\n\t" \
            "mbarrier.try_wait.parity.acquire.cta.shared::cta.b64 P1, [%0], %1, 0x989680;\n\t" \
            "@P1 bra.uni WD_%=;\n\tbra.uni WL_%=;\n\tWD_%=:\n\t}" \
            :: "r"(_mb), "r"(_p) : "memory"); \
    } } while (0)

__device__ __forceinline__ uint32_t pkbf2_(float x, float y) {
    uint32_t lo = (uint32_t)__bfloat16_as_ushort(__float2bfloat16(x));
    uint32_t hi = (uint32_t)__bfloat16_as_ushort(__float2bfloat16(y));
    return lo | (hi << 16);
}
__device__ __forceinline__ float lof_(float x) {
    return x - __bfloat162float(__float2bfloat16(x));
}

// ---------------- zero initial state + barrier ----------------
__global__ void zero_state_kernel() {
    int i = blockIdx.x * blockDim.x + threadIdx.x;
    if (i < 2 * 512 * 32) ((uint32_t*)g_hwp)[i] = 0u;   // zero g_hwp[0] hi+lo
    if (i == 0) g_bar = 0u;
}

// ---------------- fp32 -> (bf16 hi/lo), LAYOUT: 0=A-frag 1=B-frag 2=linear ----
template <int SEL, int KD, int ROWS, int LAYOUT>
__global__ void conv_pad_kernel(const float* __restrict__ src, int n_src) {
    __nv_bfloat16* hi = sel_hi<SEL>();
    __nv_bfloat16* lo = sel_lo<SEL>();
    int i = blockIdx.x * blockDim.x + threadIdx.x;
    if (i >= ROWS * KD) return;
    float v = (i < n_src) ? src[i] : 0.f;
    __nv_bfloat16 h = __float2bfloat16(v);
    __nv_bfloat16 l = __float2bfloat16(v - __bfloat162float(h));
    size_t d;
    if (LAYOUT == 2) {
        d = i;
    } else {
        int row = i / KD, k = i - row * KD;
        d = (LAYOUT == 0) ? a_frag_idx(row, k, ROWS) : b_frag_idx(row, k, ROWS);
    }
    hi[d] = h;
    lo[d] = l;
}

// ---------------- gather embedding rows + split-convert (B-frag dst) ----------------
template <int KDIM, int MODE>
__global__ void gather_conv_kernel(const int* __restrict__ idx,
                                   const float* __restrict__ emb) {
    __nv_bfloat16* hi = sel_hi<(MODE == 0) ? 3 : 4>();
    __nv_bfloat16* lo = sel_lo<(MODE == 0) ? 3 : 4>();
    int i = blockIdx.x * blockDim.x + threadIdx.x;
    if (i >= TB * KDIM) return;
    int r = i / KDIM, k = i - r * KDIM;
    int row;
    if (MODE == 0) {
        row = idx[r];
    } else {
        int t = r >> 5, b = r & 31;
        row = (t == 0) ? 1 : idx[b * TT + t - 1];
    }
    float v = emb[(size_t)row * KDIM + k];
    __nv_bfloat16 h = __float2bfloat16(v);
    size_t d = b_frag_idx(r, k, TB);
    hi[d] = h;
    lo[d] = __float2bfloat16(v - __bfloat162float(h));
}

// ---------------- split-bf16 GEMM, fragment-order operands, bulk staged ----------------
#define OPBA 8192
#define BUFB (4 * OPBA)
#define MM_SMEM (1024 + 2 * BUFB)

template <int KDIM, int BIASMODE, int ASEL, int BSEL, int OUTSEL,
          int AROWS, int BROWS>
__global__ __launch_bounds__(256) void mma_gemm_kernel(
    float* __restrict__ out_param, int ldout, int nvalid,
    const float* __restrict__ bn,
    const float* __restrict__ bm1, const float* __restrict__ bm2)
{
    constexpr int NC = KDIM / 32;
    extern __shared__ char smem[];
    uint32_t sb = smem_u32(smem);
    uint32_t mb0 = sb, mb1 = sb + 8;

    float* out = (OUTSEL == 0) ? out_param : (OUTSEL == 1) ? g_xg_enc : g_xg_dec;

    const int tid = threadIdx.x, lane = tid & 31, wid = tid >> 5;
    const int wm = wid & 1, wn = wid >> 1;
    const int mBase = blockIdx.y * 128, nBase = blockIdx.x * 128;

    const __nv_bfloat16* srcs[4] = {sel_hi<ASEL>(), sel_lo<ASEL>(),
                                    sel_hi<BSEL>(), sel_lo<BSEL>()};

    if (tid == 0) { MBAR_INIT(mb0, 1); MBAR_INIT(mb1, 1); }
    __syncthreads();

    auto issue = [&](int c, int buf) {
        if (tid == 0) {
            uint32_t mb = buf ? mb1 : mb0;
            MBAR_EXPECT_TX(mb, (uint32_t)BUFB);
#pragma unroll
            for (int op = 0; op < 4; op++) {
                size_t rows = (op < 2) ? (size_t)AROWS : (size_t)BROWS;
                int rbase = (op < 2) ? mBase : nBase;
                const char* g = (const char*)srcs[op] +
                                ((size_t)c * rows + rbase) * 64;
                CP_BULK(sb + 1024 + buf * BUFB + op * OPBA, g, (uint32_t)OPBA, mb);
            }
        }
    };

    float acc[4][4][4];
#pragma unroll
    for (int mt = 0; mt < 4; mt++)
#pragma unroll
        for (int nt = 0; nt < 4; nt++)
#pragma unroll
            for (int q = 0; q < 4; q++) acc[mt][nt][q] = 0.f;

    issue(0, 0);
    issue(1, 1);
    for (int c = 0; c < NC; c++) {
        int buf = c & 1;
        MBAR_WAIT(buf ? mb1 : mb0, (c >> 1) & 1);

        uint32_t sbb = sb + 1024 + buf * BUFB;
        uint32_t sAh = sbb, sAl = sbb + OPBA;
        uint32_t sBh = sbb + 2 * OPBA, sBl = sbb + 3 * OPBA;

#pragma unroll
        for (int ks = 0; ks < 2; ks++) {
            uint2 bh[4], bl[4];
#pragma unroll
            for (int ntl = 0; ntl < 4; ntl++) {
                uint32_t off = (uint32_t)(((wn * 4 + ntl) * 2 + ks) * 256 + lane * 8);
                bh[ntl] = *(const uint2*)(smem + (sBh - sb) + off);
                bl[ntl] = *(const uint2*)(smem + (sBl - sb) + off);
            }
#pragma unroll
            for (int mtl = 0; mtl < 4; mtl++) {
                uint32_t off = (uint32_t)(((wm * 4 + mtl) * 2 + ks) * 512 + lane * 16);
                uint4 ah = *(const uint4*)(smem + (sAh - sb) + off);
                uint4 al = *(const uint4*)(smem + (sAl - sb) + off);
#pragma unroll
                for (int ntl = 0; ntl < 4; ntl++) {
                    MMA16816(acc[mtl][ntl], ah.x, ah.y, ah.z, ah.w,
                             bh[ntl].x, bh[ntl].y);
                    MMA16816(acc[mtl][ntl], ah.x, ah.y, ah.z, ah.w,
                             bl[ntl].x, bl[ntl].y);
                    MMA16816(acc[mtl][ntl], al.x, al.y, al.z, al.w,
                             bh[ntl].x, bh[ntl].y);
                }
            }
        }
        __syncthreads();
        if (c + 2 < NC) issue(c + 2, buf);
    }

#pragma unroll
    for (int mt = 0; mt < 4; mt++) {
        int m0 = mBase + wm * 64 + mt * 16 + (lane >> 2);
#pragma unroll
        for (int half = 0; half < 2; half++) {
            int gm = m0 + half * 8;
            float bm = 0.f;
            if (BIASMODE == 1) bm = bm1[gm] + bm2[gm];
#pragma unroll
            for (int nt = 0; nt < 4; nt++) {
                int gn = nBase + wn * 32 + nt * 8 + (lane & 3) * 2;
                float v0 = acc[mt][nt][half * 2 + 0];
                float v1 = acc[mt][nt][half * 2 + 1];
                if (BIASMODE == 0) {
                    if (gn < nvalid) {
                        float2 o = make_float2(v0 + bn[gn], v1 + bn[gn + 1]);
                        *(float2*)&out[(size_t)gm * ldout + gn] = o;
                    }
                } else {
                    float2 o = make_float2(v0 + bm, v1 + bm);
                    *(float2*)&out[(size_t)gm * ldout + gn] = o;
                }
            }
        }
    }
}

// ---------------- persistent split-bf16 HMMA LSTM recurrence ----------------
// h exchange kp-major [hl][kp][b]: contiguous 1KB warp-slabs (dense L1tex lines),
// XOR-8(b, kp&3) smem swizzle for conflict-free B-fragment LDS.
#define SM_WFRAG 0                      // 131072
#define SM_HBUF  131072                 // 8 warps x 2 bufs x 2KB = 32768
#define SM_CRED  163840                 // 32768
#define SM_CS    196608                 // 1024
#define SM_HT    197632                 // 1024
#define SM_TOT   198656

__global__ __launch_bounds__(256, 1) void lstm_hmma_kernel()
{
    extern __shared__ char sm8[];
    const int tid = threadIdx.x, lane = tid & 31, w = tid >> 5;
    const int jbase = blockIdx.x * 8;
    float* c_s  = (float*)(sm8 + SM_CS);
    float* htmp = (float*)(sm8 + SM_HT);
    float* cred = (float*)(sm8 + SM_CRED);

    auto stage_w = [&](int phase) {
        const uint32_t* whi = (const uint32_t*)(phase ? g_whhd_hi : g_whhe_hi);
        const uint32_t* wlo = (const uint32_t*)(phase ? g_whhd_lo : g_whhe_lo);
        for (int ss = tid; ss < 8192; ss += 256) {
            int ls = ss & 31, hl = (ss >> 5) & 1, mt = (ss >> 6) & 1, kk = ss >> 7;
            const uint32_t* W2 = hl ? wlo : whi;
            int r0 = mt * 16 + (ls >> 2);
            int kw0 = kk * 8 + (ls & 3);
            int gA = (r0 & 3) * HH + jbase + (r0 >> 2);
            int gB = ((r0 + 8) & 3) * HH + jbase + ((r0 + 8) >> 2);
            uint4 v;
            v.x = W2[(size_t)gA * 512 + kw0];
            v.y = W2[(size_t)gB * 512 + kw0];
            v.z = W2[(size_t)gA * 512 + kw0 + 4];
            v.w = W2[(size_t)gB * 512 + kw0 + 4];
            *(uint4*)(sm8 + SM_WFRAG + ss * 16) = v;
        }
    };

    stage_w(0);
    c_s[tid] = 0.f;
    __syncthreads();

    for (int s = 0; s < 256; s++) {
        if (s == 128) { __syncthreads(); stage_w(1); __syncthreads(); }
        const int pp = s & 1, t = s & 127;
        const uint32_t* hsrc0 = g_hwp[pp][0];
        const uint32_t* hsrc1 = g_hwp[pp][1];

        // stage group g: 8 kp x 32 b, hi+lo, contiguous 1KB slabs per hl
        auto stage_h = [&](int g) {
            char* dst0 = sm8 + SM_HBUF + w * 4096 + (g & 1) * 2048;
#pragma unroll
            for (int u = 0; u < 4; u++) {
                int ee = u * 32 + lane;            // 0..127
                int hl = ee >> 6, rem = ee & 63;   // 64 x 16B per hl
                int kp_loc = rem >> 3;             // 0..7
                int b0 = (rem & 7) * 4;            // 0..28
                const uint32_t* src = (hl ? hsrc1 : hsrc0)
                    + (w * 64 + g * 8 + kp_loc) * 32 + b0;
                uint32_t sa = smem_u32(dst0 + hl * 1024 +
                    (kp_loc * 32 + (b0 ^ ((kp_loc & 3) * 8))) * 4);
                CP_ASYNC16(sa, src);
            }
            CP_COMMIT();
        };

        float acc[2][4][4];
#pragma unroll
        for (int mt = 0; mt < 2; mt++)
#pragma unroll
            for (int nt = 0; nt < 4; nt++)
#pragma unroll
                for (int q = 0; q < 4; q++) acc[mt][nt][q] = 0.f;

        stage_h(0);
#pragma unroll
        for (int g = 0; g < 8; g++) {
            if (g < 7) { stage_h(g + 1); CP_WAIT1(); } else { CP_WAIT0(); }
            int sbase = SM_WFRAG + (w * 8 + g) * 2048;
            uint4 AH0 = *(uint4*)(sm8 + sbase + lane * 16);
            uint4 AL0 = *(uint4*)(sm8 + sbase + 512 + lane * 16);
            uint4 AH1 = *(uint4*)(sm8 + sbase + 1024 + lane * 16);
            uint4 AL1 = *(uint4*)(sm8 + sbase + 1536 + lane * 16);
            char* hb = sm8 + SM_HBUF + w * 4096 + (g & 1) * 2048;
            int kpa = (lane & 3), kpb = (lane & 3) + 4;
#pragma unroll
            for (int nt = 0; nt < 4; nt++) {
                int bswz = (nt * 8 + (lane >> 2)) ^ ((lane & 3) * 8);
                uint32_t bh0 = *(uint32_t*)(hb + (kpa * 32 + bswz) * 4);
                uint32_t bh1 = *(uint32_t*)(hb + (kpb * 32 + bswz) * 4);
                uint32_t bl0 = *(uint32_t*)(hb + 1024 + (kpa * 32 + bswz) * 4);
                uint32_t bl1 = *(uint32_t*)(hb + 1024 + (kpb * 32 + bswz) * 4);
                MMA16816(acc[0][nt], AH0.x, AH0.y, AH0.z, AH0.w, bh0, bh1);
                MMA16816(acc[1][nt], AH1.x, AH1.y, AH1.z, AH1.w, bh0, bh1);
                MMA16816(acc[0][nt], AH0.x, AH0.y, AH0.z, AH0.w, bl0, bl1);
                MMA16816(acc[1][nt], AH1.x, AH1.y, AH1.z, AH1.w, bl0, bl1);
                MMA16816(acc[0][nt], AL0.x, AL0.y, AL0.z, AL0.w, bh0, bh1);
                MMA16816(acc[1][nt], AL1.x, AL1.y, AL1.z, AL1.w, bh0, bh1);
            }
        }

#pragma unroll
        for (int mt = 0; mt < 2; mt++)
#pragma unroll
            for (int nt = 0; nt < 4; nt++) {
                int rlo = mt * 16 + (lane >> 2);
                int c0 = nt * 8 + (lane & 3) * 2;
                int r1 = rlo, r2 = rlo + 8;
                int s1 = (r1 & 7) << 2, s2 = (r2 & 7) << 2;
                *(float2*)&cred[(w * 32 + r1) * 32 + (c0 ^ s1)] =
                    make_float2(acc[mt][nt][0], acc[mt][nt][1]);
                *(float2*)&cred[(w * 32 + r2) * 32 + (c0 ^ s2)] =
                    make_float2(acc[mt][nt][2], acc[mt][nt][3]);
            }
        __syncthreads();

        {
            int b = tid & 31, jx = tid >> 5;
            const float* xg = (s < 128) ? g_xg_enc : g_xg_dec;
            float sg[4];
#pragma unroll
            for (int gg = 0; gg < 4; gg++) {
                int row = jx * 4 + gg;
                int sw = (row & 7) << 2;
                float v = xg[(size_t)(gg * HH + jbase + jx) * TB + t * 32 + b];
#pragma unroll
                for (int ww = 0; ww < 8; ww++)
                    v += cred[(ww * 32 + row) * 32 + (b ^ sw)];
                sg[gg] = v;
            }
            float ig = sigmoidf_(sg[0]);
            float fg = sigmoidf_(sg[1]);
            float gv = tanhf(sg[2]);
            float og = sigmoidf_(sg[3]);
            float c = fg * c_s[jx * 32 + b] + ig * gv;
            c_s[jx * 32 + b] = c;
            float h = og * tanhf(c);
            htmp[jx * 32 + b] = h;
            if (s >= 128) {
                int rr = t * 32 + b;
                int j = jbase + jx;
                size_t d = a_frag_idx(rr, j, TB);
                __nv_bfloat16 hb16 = __float2bfloat16(h);
                g_hs_hi[d] = hb16;
                g_hs_lo[d] = __float2bfloat16(h - __bfloat162float(hb16));
            }
        }
        __syncthreads();

        // pack h -> kp-major [hl][kp][b] (coalesced 128B stores per kp)
        {
            int hl = tid >> 7, q = tid & 127;
            int kpl = q >> 5, b = q & 31;
            float h0 = htmp[(2 * kpl) * 32 + b];
            float h1 = htmp[(2 * kpl + 1) * 32 + b];
            uint32_t word;
            if (hl == 0) {
                word = pkbf2_(h0, h1);
            } else {
                word = pkbf2_(lof_(h0), lof_(h1));
            }
            g_hwp[pp ^ 1][hl][((jbase >> 1) + kpl) * 32 + b] = word;
        }
        __syncthreads();

        if (tid == 0) {
            unsigned old;
            asm volatile("atom.release.gpu.global.add.u32 %0, [%1], 1;"
                         : "=r"(old) : "l"(&g_bar) : "memory");
            unsigned target = (unsigned)(s + 1) * GRID_P;
            unsigned v;
            do {
                asm volatile("ld.acquire.gpu.global.u32 %0, [%1];"
                             : "=r"(v) : "l"(&g_bar) : "memory");
            } while (v < target);
        }
        __syncthreads();
    }
}

// ---------------- host launcher ----------------
extern "C" void kernel_launch(void* const* d_in, const int* in_sizes, int n_in,
                              void* d_out, int out_size)
{
    const int*   sentence  = (const int*)d_in[0];
    const int*   label_seq = (const int*)d_in[1];
    const float* word_emb  = (const float*)d_in[2];
    const float* label_emb = (const float*)d_in[3];
    const float* enc_W_ih  = (const float*)d_in[4];
    const float* enc_W_hh  = (const float*)d_in[5];
    const float* enc_b_ih  = (const float*)d_in[6];
    const float* enc_b_hh  = (const float*)d_in[7];
    const float* dec_W_ih  = (const float*)d_in[8];
    const float* dec_W_hh  = (const float*)d_in[9];
    const float* dec_b_ih  = (const float*)d_in[10];
    const float* dec_b_hh  = (const float*)d_in[11];
    const float* W_score   = (const float*)d_in[12];
    const float* b_score   = (const float*)d_in[13];
    float* out = (float*)d_out;

    cudaFuncSetAttribute(lstm_hmma_kernel,
                         cudaFuncAttributeMaxDynamicSharedMemorySize, SM_TOT);
    cudaFuncSetAttribute(mma_gemm_kernel<EE, 1, 1, 3, 1, G4, TB>,
                         cudaFuncAttributeMaxDynamicSharedMemorySize, MM_SMEM);
    cudaFuncSetAttribute(mma_gemm_kernel<LDIM, 1, 2, 4, 2, G4, TB>,
                         cudaFuncAttributeMaxDynamicSharedMemorySize, MM_SMEM);
    cudaFuncSetAttribute(mma_gemm_kernel<HH, 0, 5, 0, 0, TB, LLP>,
                         cudaFuncAttributeMaxDynamicSharedMemorySize, MM_SMEM);

    zero_state_kernel<<<32, 1024>>>();
    conv_pad_kernel<1, EE, G4, 0><<<(G4 * EE + 255) / 256, 256>>>(enc_W_ih, G4 * EE);
    gather_conv_kernel<EE, 0><<<(TB * EE + 255) / 256, 256>>>(sentence, word_emb);
    mma_gemm_kernel<EE, 1, 1, 3, 1, G4, TB><<<dim3(TB / 128, G4 / 128), 256, MM_SMEM>>>(
        nullptr, TB, TB, nullptr, enc_b_ih, enc_b_hh);
    conv_pad_kernel<2, LDIM, G4, 0><<<(G4 * LDIM + 255) / 256, 256>>>(dec_W_ih, G4 * LDIM);
    gather_conv_kernel<LDIM, 1><<<(TB * LDIM + 255) / 256, 256>>>(label_seq, label_emb);
    mma_gemm_kernel<LDIM, 1, 2, 4, 2, G4, TB><<<dim3(TB / 128, G4 / 128), 256, MM_SMEM>>>(
        nullptr, TB, TB, nullptr, dec_b_ih, dec_b_hh);
    conv_pad_kernel<0, HH, LLP, 1><<<(LLP * HH + 255) / 256, 256>>>(W_score, LL * HH);
    conv_pad_kernel<6, HH, G4, 2><<<(G4 * HH + 255) / 256, 256>>>(enc_W_hh, G4 * HH);
    conv_pad_kernel<7, HH, G4, 2><<<(G4 * HH + 255) / 256, 256>>>(dec_W_hh, G4 * HH);

    // recurrence (persistent, split-bf16 HMMA, kp-major h exchange)
    lstm_hmma_kernel<<<GRID_P, 256, SM_TOT>>>();

    // projection: out[r][l] = hs @ Ws^T + b_score
    mma_gemm_kernel<HH, 0, 5, 0, 0, TB, LLP><<<dim3(LLP / 128, TB / 128), 256, MM_SMEM>>>(
        out, LL, LL, b_score, nullptr, nullptr);
}